// round 3
// baseline (speedup 1.0000x reference)
#include <cuda_runtime.h>
#include <cuda_fp16.h>

// ---------------------------------------------------------------------------
// Static device scratch (no allocations allowed).
// N = 100000 nodes, E = 1600000 edges, D = 128.
// ---------------------------------------------------------------------------
#define MAX_NODES 100000
#define MAX_EDGES 1600000
#define SCAN_ELEMS 512
#define SCAN_BLOCKS ((MAX_NODES + SCAN_ELEMS - 1) / SCAN_ELEMS)  // 196

__device__ __align__(16) int    g_cnt[MAX_NODES];          // in-degree histogram
__device__ __align__(16) int    g_off[MAX_NODES + 4];      // exclusive CSR offsets
__device__ __align__(16) int    g_cur[MAX_NODES];          // fill cursors (= off copy)
__device__ __align__(16) int    g_srcs[MAX_EDGES];         // src ids sorted by dst
__device__ __align__(16) __half g_half[(size_t)MAX_NODES * 128];  // fp16 feats copy
__device__ unsigned long long   g_state[SCAN_BLOCKS];      // lookback status words
__device__ unsigned             g_ticket;                  // scan block ticket

// ---------------------------------------------------------------------------
// 1. prep: convert feats fp32 -> fp16 (same node*32+lane float4 layout:
//    uint2 = 4 halfs), zero histogram + scan state + ticket, set off[n] = E.
// ---------------------------------------------------------------------------
__global__ void prep_kernel(const float4* __restrict__ feats4,
                            uint2* __restrict__ half4,
                            int* __restrict__ cnt,
                            long nf4, int n_nodes, int n_edges) {
    long i = (long)blockIdx.x * blockDim.x + threadIdx.x;
    long stride = (long)gridDim.x * blockDim.x;
    for (long j = i; j < nf4; j += stride) {
        float4 v = __ldg(feats4 + j);
        __half2 a = __floats2half2_rn(v.x, v.y);
        __half2 b = __floats2half2_rn(v.z, v.w);
        uint2 o;
        o.x = *reinterpret_cast<unsigned*>(&a);
        o.y = *reinterpret_cast<unsigned*>(&b);
        half4[j] = o;
    }
    for (long j = i; j < n_nodes; j += stride) cnt[j] = 0;
    for (long j = i; j < SCAN_BLOCKS; j += stride) g_state[j] = 0ULL;
    if (i == 0) { g_ticket = 0u; g_off[n_nodes] = n_edges; }
}

// ---------------------------------------------------------------------------
// 2. histogram of dst (int4-vectorized loads)
// ---------------------------------------------------------------------------
__global__ void hist_kernel(const int* __restrict__ dst, int* __restrict__ cnt,
                            int n_edges) {
    int i = blockIdx.x * blockDim.x + threadIdx.x;
    int base = i * 4;
    if (base + 3 < n_edges) {
        int4 d = __ldg(reinterpret_cast<const int4*>(dst) + i);
        atomicAdd(cnt + d.x, 1);
        atomicAdd(cnt + d.y, 1);
        atomicAdd(cnt + d.z, 1);
        atomicAdd(cnt + d.w, 1);
    } else {
        for (int e = base; e < n_edges; e++) atomicAdd(cnt + __ldg(dst + e), 1);
    }
}

// ---------------------------------------------------------------------------
// 3. single-pass exclusive scan (decoupled lookback), writes off[] AND cur[].
//    Status word: bits[1:0] flag (0=invalid,1=aggregate,2=inclusive-prefix),
//    bits[63:2] value. Single-word publish => atomic, no fence needed.
// ---------------------------------------------------------------------------
__device__ __forceinline__ int warp_incl_scan(int v, int lane) {
#pragma unroll
    for (int o = 1; o < 32; o <<= 1) {
        int n = __shfl_up_sync(0xffffffffu, v, o);
        if (lane >= o) v += n;
    }
    return v;
}

__global__ void scan_kernel(const int* __restrict__ cnt,
                            int* __restrict__ off,
                            int* __restrict__ cur, int n) {
    __shared__ int sh_bid;
    __shared__ int sh_prefix;
    __shared__ int wsum[4];
    int t = threadIdx.x;
    if (t == 0) sh_bid = (int)atomicAdd(&g_ticket, 1u);
    __syncthreads();
    int bid = sh_bid;
    int lane = t & 31, warp = t >> 5;
    int base = bid * SCAN_ELEMS + t * 4;

    int4 v = make_int4(0, 0, 0, 0);
    if (base < n) v = *reinterpret_cast<const int4*>(cnt + base);  // n % 4 == 0

    int tsum = v.x + v.y + v.z + v.w;
    int incl = warp_incl_scan(tsum, lane);
    if (lane == 31) wsum[warp] = incl;
    __syncthreads();
    int wpre = 0;
#pragma unroll
    for (int w = 0; w < 4; w++) if (w < warp) wpre += wsum[w];
    int texcl = incl - tsum + wpre;
    int agg = wsum[0] + wsum[1] + wsum[2] + wsum[3];

    if (t == 0) {
        if (bid == 0) {
            atomicExch(&g_state[0], ((unsigned long long)agg << 2) | 2ULL);
            sh_prefix = 0;
        } else {
            atomicExch(&g_state[bid], ((unsigned long long)agg << 2) | 1ULL);
            int sum = 0;
            int j = bid - 1;
            while (true) {
                unsigned long long s = atomicAdd(&g_state[j], 0ULL);
                unsigned f = (unsigned)(s & 3ULL);
                if (f == 2u) { sum += (int)(s >> 2); break; }
                if (f == 1u) { sum += (int)(s >> 2); j--; }
                // f == 0: spin
            }
            sh_prefix = sum;
            atomicExch(&g_state[bid],
                       ((unsigned long long)(sum + agg) << 2) | 2ULL);
        }
    }
    __syncthreads();
    int pre = sh_prefix;

    if (base < n) {
        int4 o;
        o.x = texcl + pre;
        o.y = o.x + v.x;
        o.z = o.y + v.y;
        o.w = o.z + v.z;
        *reinterpret_cast<int4*>(off + base) = o;
        *reinterpret_cast<int4*>(cur + base) = o;   // fill cursors start at off
    }
}

// ---------------------------------------------------------------------------
// 4. fill: counting-sort src ids into dst buckets (cursor IS the position)
// ---------------------------------------------------------------------------
__global__ void fill_kernel(const int* __restrict__ src,
                            const int* __restrict__ dst,
                            int* __restrict__ cur,
                            int* __restrict__ srcs, int n_edges) {
    int e = blockIdx.x * blockDim.x + threadIdx.x;
    if (e >= n_edges) return;
    int d = __ldg(dst + e);
    int p = atomicAdd(cur + d, 1);
    srcs[p] = __ldg(src + e);
}

// ---------------------------------------------------------------------------
// 5. gather + finalize: one warp per node. fp16 message rows (256B), fp32
//    accumulate, exact fp32 residual. Lane owns feature dims [lane*4, lane*4+4).
//    out = 0.5*x + 0.5*sum/max(deg,1)
// ---------------------------------------------------------------------------
__global__ void gather_kernel(const float4* __restrict__ feats4,
                              const uint2* __restrict__ half4,
                              const int* __restrict__ off,
                              const int* __restrict__ srcs,
                              float4* __restrict__ out4, int n_nodes) {
    int tid = blockIdx.x * blockDim.x + threadIdx.x;
    int node = tid >> 5;
    int lane = tid & 31;
    if (node >= n_nodes) return;

    int beg = __ldg(off + node);
    int end = __ldg(off + node + 1);

    float4 acc = make_float4(0.f, 0.f, 0.f, 0.f);
    for (int base = beg; base < end; base += 32) {
        int nchunk = min(32, end - base);
        int idx = (lane < nchunk) ? __ldg(srcs + base + lane) : 0;
        for (int j = 0; j < nchunk; j++) {
            int s = __shfl_sync(0xffffffffu, idx, j);
            uint2 u = __ldg(half4 + (size_t)s * 32 + lane);
            __half2 h0 = *reinterpret_cast<__half2*>(&u.x);
            __half2 h1 = *reinterpret_cast<__half2*>(&u.y);
            float2 f0 = __half22float2(h0);
            float2 f1 = __half22float2(h1);
            acc.x += f0.x; acc.y += f0.y; acc.z += f1.x; acc.w += f1.y;
        }
    }

    float deg = (float)(end - beg);
    float inv = 0.5f / fmaxf(deg, 1.0f);     // fold (1-alpha)=0.5 into divide
    float4 x = __ldg(feats4 + (size_t)node * 32 + lane);
    float4 r;
    r.x = 0.5f * x.x + inv * acc.x;
    r.y = 0.5f * x.y + inv * acc.y;
    r.z = 0.5f * x.z + inv * acc.z;
    r.w = 0.5f * x.w + inv * acc.w;
    out4[(size_t)node * 32 + lane] = r;
}

// ---------------------------------------------------------------------------
// Launch: d_in[0]=edge_feats [N*128] f32, d_in[1]=src [E] i32, d_in[2]=dst [E] i32
// ---------------------------------------------------------------------------
extern "C" void kernel_launch(void* const* d_in, const int* in_sizes, int n_in,
                              void* d_out, int out_size) {
    const float* feats = (const float*)d_in[0];
    const int* src = (const int*)d_in[1];
    const int* dst = (const int*)d_in[2];
    float* out = (float*)d_out;

    const int D = 128;
    const int n_nodes = in_sizes[0] / D;
    const int n_edges = in_sizes[1];
    const long nf4 = (long)n_nodes * (D / 4);

    int *cnt, *off, *cur, *srcs;
    __half* halfp;
    cudaGetSymbolAddress((void**)&cnt, g_cnt);
    cudaGetSymbolAddress((void**)&off, g_off);
    cudaGetSymbolAddress((void**)&cur, g_cur);
    cudaGetSymbolAddress((void**)&srcs, g_srcs);
    cudaGetSymbolAddress((void**)&halfp, g_half);

    int scan_blocks = (n_nodes + SCAN_ELEMS - 1) / SCAN_ELEMS;

    // 1. convert + zero
    prep_kernel<<<2048, 256>>>((const float4*)feats, (uint2*)halfp, cnt,
                               nf4, n_nodes, n_edges);
    // 2. histogram
    hist_kernel<<<(n_edges / 4 + 255) / 256, 256>>>(dst, cnt, n_edges);
    // 3. single-pass scan -> off + cur
    scan_kernel<<<scan_blocks, 128>>>(cnt, off, cur, n_nodes);
    // 4. bucket fill
    fill_kernel<<<(n_edges + 255) / 256, 256>>>(src, dst, cur, srcs, n_edges);
    // 5. fp16 pull-gather + fp32 finalize
    {
        long total = (long)n_nodes * 32;
        gather_kernel<<<(int)((total + 255) / 256), 256>>>(
            (const float4*)feats, (const uint2*)halfp, off, srcs,
            (float4*)out, n_nodes);
    }
}

// round 4
// speedup vs baseline: 1.0009x; 1.0009x over previous
#include <cuda_runtime.h>
#include <cuda_fp16.h>

// ---------------------------------------------------------------------------
// Static device scratch (no allocations allowed). Zero-initialized at module
// load; every kernel_launch invocation leaves cnt/state/ticket re-zeroed
// (done by gather_kernel, after scan has consumed them) so each call sees
// identical initial state -> deterministic.
// N = 100000 nodes, E = 1600000 edges, D = 128.
// ---------------------------------------------------------------------------
#define MAX_NODES 100000
#define MAX_EDGES 1600000
#define SCAN_ELEMS 512
#define SCAN_BLOCKS ((MAX_NODES + SCAN_ELEMS - 1) / SCAN_ELEMS)  // 196

__device__ __align__(16) int    g_cnt[MAX_NODES];          // in-degree histogram
__device__ __align__(16) int    g_off[MAX_NODES + 4];      // exclusive CSR offsets
__device__ __align__(16) int    g_cur[MAX_NODES];          // fill cursors
__device__ __align__(16) int    g_srcs[MAX_EDGES];         // src ids sorted by dst
__device__ __align__(16) __half g_half[(size_t)MAX_NODES * 128];  // fp16 feats
__device__ unsigned long long   g_state[SCAN_BLOCKS];      // lookback status
__device__ unsigned             g_ticket;                  // scan block ticket

// ---------------------------------------------------------------------------
// 1. prep_hist: fp32->fp16 convert (bandwidth-bound) fused with dst histogram
//    (atomic-pipe-bound, RED no-return). cnt is zero on entry (see above).
// ---------------------------------------------------------------------------
__global__ void prep_hist_kernel(const float4* __restrict__ feats4,
                                 uint2* __restrict__ half4,
                                 const int4* __restrict__ dst4,
                                 int* __restrict__ cnt,
                                 long nf4, int ne4, int n_edges) {
    long i = (long)blockIdx.x * blockDim.x + threadIdx.x;
    long stride = (long)gridDim.x * blockDim.x;

    // histogram first: RED ops launch and retire without blocking the convert
    for (long j = i; j < ne4; j += stride) {
        int4 d = __ldg(dst4 + j);
        atomicAdd(cnt + d.x, 1);   // result unused -> REDG
        atomicAdd(cnt + d.y, 1);
        atomicAdd(cnt + d.z, 1);
        atomicAdd(cnt + d.w, 1);
    }
    if (i == 0) {
        for (int e = ne4 * 4; e < n_edges; e++)
            atomicAdd(cnt + ((const int*)dst4)[e], 1);
        g_off[MAX_NODES] = 0;  // unused slot; sentinel set properly below
    }

    for (long j = i; j < nf4; j += stride) {
        float4 v = __ldg(feats4 + j);
        __half2 a = __floats2half2_rn(v.x, v.y);
        __half2 b = __floats2half2_rn(v.z, v.w);
        uint2 o;
        o.x = *reinterpret_cast<unsigned*>(&a);
        o.y = *reinterpret_cast<unsigned*>(&b);
        half4[j] = o;
    }
}

// ---------------------------------------------------------------------------
// 2. single-pass exclusive scan (decoupled lookback) -> off[] and cur[].
//    Status word: bits[1:0] flag (1=aggregate, 2=inclusive-prefix), value<<2.
// ---------------------------------------------------------------------------
__device__ __forceinline__ int warp_incl_scan(int v, int lane) {
#pragma unroll
    for (int o = 1; o < 32; o <<= 1) {
        int n = __shfl_up_sync(0xffffffffu, v, o);
        if (lane >= o) v += n;
    }
    return v;
}

__global__ void scan_kernel(const int* __restrict__ cnt,
                            int* __restrict__ off,
                            int* __restrict__ cur, int n, int n_edges) {
    __shared__ int sh_bid;
    __shared__ int sh_prefix;
    __shared__ int wsum[4];
    int t = threadIdx.x;
    if (t == 0) sh_bid = (int)atomicAdd(&g_ticket, 1u);
    __syncthreads();
    int bid = sh_bid;
    int lane = t & 31, warp = t >> 5;
    int base = bid * SCAN_ELEMS + t * 4;

    int4 v = make_int4(0, 0, 0, 0);
    if (base < n) v = *reinterpret_cast<const int4*>(cnt + base);  // n % 4 == 0

    int tsum = v.x + v.y + v.z + v.w;
    int incl = warp_incl_scan(tsum, lane);
    if (lane == 31) wsum[warp] = incl;
    __syncthreads();
    int wpre = 0;
#pragma unroll
    for (int w = 0; w < 4; w++) if (w < warp) wpre += wsum[w];
    int texcl = incl - tsum + wpre;
    int agg = wsum[0] + wsum[1] + wsum[2] + wsum[3];

    if (t == 0) {
        if (bid == 0) {
            atomicExch(&g_state[0], ((unsigned long long)agg << 2) | 2ULL);
            sh_prefix = 0;
        } else {
            atomicExch(&g_state[bid], ((unsigned long long)agg << 2) | 1ULL);
            int sum = 0;
            int j = bid - 1;
            while (true) {
                unsigned long long s = atomicAdd(&g_state[j], 0ULL);
                unsigned f = (unsigned)(s & 3ULL);
                if (f == 2u) { sum += (int)(s >> 2); break; }
                if (f == 1u) { sum += (int)(s >> 2); j--; }
            }
            sh_prefix = sum;
            atomicExch(&g_state[bid],
                       ((unsigned long long)(sum + agg) << 2) | 2ULL);
        }
    }
    __syncthreads();
    int pre = sh_prefix;

    if (base < n) {
        int4 o;
        o.x = texcl + pre;
        o.y = o.x + v.x;
        o.z = o.y + v.y;
        o.w = o.z + v.z;
        *reinterpret_cast<int4*>(off + base) = o;
        *reinterpret_cast<int4*>(cur + base) = o;
    }
    if (bid == 0 && t == 0) off[n] = n_edges;   // sentinel
}

// ---------------------------------------------------------------------------
// 3. fill: counting-sort src ids into dst buckets. 4 edges per thread via
//    int4 loads -> 4 independent ATOMGs in flight (MLP=4, was the R3
//    bottleneck: issue=4.7%, one 318-cyc atomic per thread).
// ---------------------------------------------------------------------------
__global__ void fill_kernel(const int4* __restrict__ src4,
                            const int4* __restrict__ dst4,
                            int* __restrict__ cur,
                            int* __restrict__ srcs, int ne4, int n_edges) {
    int i = blockIdx.x * blockDim.x + threadIdx.x;
    if (i < ne4) {
        int4 d = __ldg(dst4 + i);
        int4 s = __ldg(src4 + i);
        int p0 = atomicAdd(cur + d.x, 1);
        int p1 = atomicAdd(cur + d.y, 1);
        int p2 = atomicAdd(cur + d.z, 1);
        int p3 = atomicAdd(cur + d.w, 1);
        srcs[p0] = s.x;
        srcs[p1] = s.y;
        srcs[p2] = s.z;
        srcs[p3] = s.w;
    }
    if (i == 0) {
        const int* src = (const int*)src4;
        const int* dst = (const int*)dst4;
        for (int e = ne4 * 4; e < n_edges; e++) {
            int p = atomicAdd(cur + dst[e], 1);
            srcs[p] = src[e];
        }
    }
}

// ---------------------------------------------------------------------------
// 4. gather + finalize + cleanup. One warp per node, fp16 messages (256B/row),
//    fp32 accumulate, exact fp32 residual. Also re-zeroes cnt/state/ticket
//    for the next invocation (scan already consumed them; stream order).
// ---------------------------------------------------------------------------
__global__ void gather_kernel(const float4* __restrict__ feats4,
                              const uint2* __restrict__ half4,
                              const int* __restrict__ off,
                              const int* __restrict__ srcs,
                              float4* __restrict__ out4,
                              int* __restrict__ cnt, int n_nodes) {
    int tid = blockIdx.x * blockDim.x + threadIdx.x;
    int total = gridDim.x * blockDim.x;

    // cleanup for next invocation (cheap: 400KB + 1.5KB + 4B)
    for (int j = tid; j < n_nodes; j += total) cnt[j] = 0;
    for (int j = tid; j < SCAN_BLOCKS; j += total) g_state[j] = 0ULL;
    if (tid == 0) g_ticket = 0u;

    int node = tid >> 5;
    int lane = tid & 31;
    if (node >= n_nodes) return;

    int beg = __ldg(off + node);
    int end = __ldg(off + node + 1);

    float4 acc = make_float4(0.f, 0.f, 0.f, 0.f);
    for (int base = beg; base < end; base += 32) {
        int nchunk = min(32, end - base);
        int idx = (lane < nchunk) ? __ldg(srcs + base + lane) : 0;
        for (int j = 0; j < nchunk; j++) {
            int s = __shfl_sync(0xffffffffu, idx, j);
            uint2 u = __ldg(half4 + (size_t)s * 32 + lane);
            __half2 h0 = *reinterpret_cast<__half2*>(&u.x);
            __half2 h1 = *reinterpret_cast<__half2*>(&u.y);
            float2 f0 = __half22float2(h0);
            float2 f1 = __half22float2(h1);
            acc.x += f0.x; acc.y += f0.y; acc.z += f1.x; acc.w += f1.y;
        }
    }

    float deg = (float)(end - beg);
    float inv = 0.5f / fmaxf(deg, 1.0f);
    float4 x = __ldg(feats4 + (size_t)node * 32 + lane);
    float4 r;
    r.x = 0.5f * x.x + inv * acc.x;
    r.y = 0.5f * x.y + inv * acc.y;
    r.z = 0.5f * x.z + inv * acc.z;
    r.w = 0.5f * x.w + inv * acc.w;
    out4[(size_t)node * 32 + lane] = r;
}

// ---------------------------------------------------------------------------
// Launch: d_in[0]=edge_feats [N*128] f32, d_in[1]=src [E] i32, d_in[2]=dst [E] i32
// ---------------------------------------------------------------------------
extern "C" void kernel_launch(void* const* d_in, const int* in_sizes, int n_in,
                              void* d_out, int out_size) {
    const float* feats = (const float*)d_in[0];
    const int* src = (const int*)d_in[1];
    const int* dst = (const int*)d_in[2];
    float* out = (float*)d_out;

    const int D = 128;
    const int n_nodes = in_sizes[0] / D;
    const int n_edges = in_sizes[1];
    const long nf4 = (long)n_nodes * (D / 4);
    const int ne4 = n_edges / 4;

    int *cnt, *off, *cur, *srcs;
    __half* halfp;
    cudaGetSymbolAddress((void**)&cnt, g_cnt);
    cudaGetSymbolAddress((void**)&off, g_off);
    cudaGetSymbolAddress((void**)&cur, g_cur);
    cudaGetSymbolAddress((void**)&srcs, g_srcs);
    cudaGetSymbolAddress((void**)&halfp, g_half);

    int scan_blocks = (n_nodes + SCAN_ELEMS - 1) / SCAN_ELEMS;

    // 1. convert + histogram (fused)
    prep_hist_kernel<<<2048, 256>>>((const float4*)feats, (uint2*)halfp,
                                    (const int4*)dst, cnt, nf4, ne4, n_edges);
    // 2. single-pass scan -> off + cur
    scan_kernel<<<scan_blocks, 128>>>(cnt, off, cur, n_nodes, n_edges);
    // 3. bucket fill (4 edges/thread)
    fill_kernel<<<(ne4 + 255) / 256, 256>>>((const int4*)src, (const int4*)dst,
                                            cur, srcs, ne4, n_edges);
    // 4. fp16 pull-gather + fp32 finalize + scratch cleanup
    {
        long total = (long)n_nodes * 32;
        gather_kernel<<<(int)((total + 255) / 256), 256>>>(
            (const float4*)feats, (const uint2*)halfp, off, srcs,
            (float4*)out, cnt, n_nodes);
    }
}

// round 5
// speedup vs baseline: 1.1055x; 1.1045x over previous
#include <cuda_runtime.h>
#include <cuda_fp16.h>

// ---------------------------------------------------------------------------
// Static device scratch (no allocations allowed).
// N = 100000 nodes, E = 1600000 edges, D = 128.
// Padded-bucket CSR: capacity 128 per node (avg in-degree 16, Poisson max
// over 100K nodes ~45 -> 128 never overflows; guarded anyway).
// ---------------------------------------------------------------------------
#define MAX_NODES 100000
#define BUCKET_CAP 128

__device__ __align__(16) int    g_cur[MAX_NODES];                   // degree/cursor
__device__ __align__(16) int    g_srcs[(size_t)MAX_NODES * BUCKET_CAP];
__device__ __align__(16) __half g_half[(size_t)MAX_NODES * 128];    // fp16 feats

// ---------------------------------------------------------------------------
// 1. prep: fp32 -> fp16 convert (bandwidth-bound) + zero cursors.
// ---------------------------------------------------------------------------
__global__ void prep_kernel(const float4* __restrict__ feats4,
                            uint2* __restrict__ half4,
                            int* __restrict__ cur,
                            long nf4, int n_nodes) {
    long i = (long)blockIdx.x * blockDim.x + threadIdx.x;
    long stride = (long)gridDim.x * blockDim.x;
    for (long j = i; j < n_nodes; j += stride) cur[j] = 0;
    for (long j = i; j < nf4; j += stride) {
        float4 v = __ldg(feats4 + j);
        __half2 a = __floats2half2_rn(v.x, v.y);
        __half2 b = __floats2half2_rn(v.z, v.w);
        uint2 o;
        o.x = *reinterpret_cast<unsigned*>(&a);
        o.y = *reinterpret_cast<unsigned*>(&b);
        half4[j] = o;
    }
}

// ---------------------------------------------------------------------------
// 2. fill: drop src ids into per-dst padded buckets. 4 edges/thread via int4
//    loads -> 4 independent ATOMGs in flight.
// ---------------------------------------------------------------------------
__global__ void fill_kernel(const int4* __restrict__ src4,
                            const int4* __restrict__ dst4,
                            int* __restrict__ cur,
                            int* __restrict__ srcs, int ne4, int n_edges) {
    int i = blockIdx.x * blockDim.x + threadIdx.x;
    if (i < ne4) {
        int4 d = __ldg(dst4 + i);
        int4 s = __ldg(src4 + i);
        int p0 = atomicAdd(cur + d.x, 1);
        int p1 = atomicAdd(cur + d.y, 1);
        int p2 = atomicAdd(cur + d.z, 1);
        int p3 = atomicAdd(cur + d.w, 1);
        if (p0 < BUCKET_CAP) srcs[(size_t)d.x * BUCKET_CAP + p0] = s.x;
        if (p1 < BUCKET_CAP) srcs[(size_t)d.y * BUCKET_CAP + p1] = s.y;
        if (p2 < BUCKET_CAP) srcs[(size_t)d.z * BUCKET_CAP + p2] = s.z;
        if (p3 < BUCKET_CAP) srcs[(size_t)d.w * BUCKET_CAP + p3] = s.w;
    }
    if (i == 0) {
        const int* src = (const int*)src4;
        const int* dst = (const int*)dst4;
        for (int e = ne4 * 4; e < n_edges; e++) {
            int d = dst[e];
            int p = atomicAdd(cur + d, 1);
            if (p < BUCKET_CAP) srcs[(size_t)d * BUCKET_CAP + p] = src[e];
        }
    }
}

// ---------------------------------------------------------------------------
// 3. gather + finalize: one warp per node, fp16 messages (256B/row), fp32
//    accumulation. Inner loop unrolled x4 with two accumulators: 4
//    independent LDG.64s in flight per thread (R4 showed issue=52%,
//    serial-chain bound). out = 0.5*x + 0.5*sum/max(deg,1).
// ---------------------------------------------------------------------------
__device__ __forceinline__ void acc_add(float4& acc, uint2 u) {
    __half2 h0 = *reinterpret_cast<__half2*>(&u.x);
    __half2 h1 = *reinterpret_cast<__half2*>(&u.y);
    float2 f0 = __half22float2(h0);
    float2 f1 = __half22float2(h1);
    acc.x += f0.x; acc.y += f0.y; acc.z += f1.x; acc.w += f1.y;
}

__global__ void gather_kernel(const float4* __restrict__ feats4,
                              const uint2* __restrict__ half4,
                              const int* __restrict__ cur,
                              const int* __restrict__ srcs,
                              float4* __restrict__ out4, int n_nodes) {
    int tid = blockIdx.x * blockDim.x + threadIdx.x;
    int node = tid >> 5;
    int lane = tid & 31;
    if (node >= n_nodes) return;

    int deg = min(__ldg(cur + node), BUCKET_CAP);
    const int* bucket = srcs + (size_t)node * BUCKET_CAP;

    float4 accA = make_float4(0.f, 0.f, 0.f, 0.f);
    float4 accB = make_float4(0.f, 0.f, 0.f, 0.f);

    for (int base = 0; base < deg; base += 32) {
        int nchunk = min(32, deg - base);
        int idx = (lane < nchunk) ? __ldg(bucket + base + lane) : 0;
        int j = 0;
        for (; j + 4 <= nchunk; j += 4) {
            int s0 = __shfl_sync(0xffffffffu, idx, j);
            int s1 = __shfl_sync(0xffffffffu, idx, j + 1);
            int s2 = __shfl_sync(0xffffffffu, idx, j + 2);
            int s3 = __shfl_sync(0xffffffffu, idx, j + 3);
            uint2 u0 = __ldg(half4 + (size_t)s0 * 32 + lane);
            uint2 u1 = __ldg(half4 + (size_t)s1 * 32 + lane);
            uint2 u2 = __ldg(half4 + (size_t)s2 * 32 + lane);
            uint2 u3 = __ldg(half4 + (size_t)s3 * 32 + lane);
            acc_add(accA, u0);
            acc_add(accB, u1);
            acc_add(accA, u2);
            acc_add(accB, u3);
        }
        for (; j < nchunk; j++) {
            int s = __shfl_sync(0xffffffffu, idx, j);
            uint2 u = __ldg(half4 + (size_t)s * 32 + lane);
            acc_add(accA, u);
        }
    }

    float4 acc;
    acc.x = accA.x + accB.x;
    acc.y = accA.y + accB.y;
    acc.z = accA.z + accB.z;
    acc.w = accA.w + accB.w;

    float inv = 0.5f / fmaxf((float)deg, 1.0f);  // fold (1-alpha)=0.5
    float4 x = __ldg(feats4 + (size_t)node * 32 + lane);
    float4 r;
    r.x = 0.5f * x.x + inv * acc.x;
    r.y = 0.5f * x.y + inv * acc.y;
    r.z = 0.5f * x.z + inv * acc.z;
    r.w = 0.5f * x.w + inv * acc.w;
    out4[(size_t)node * 32 + lane] = r;
}

// ---------------------------------------------------------------------------
// Launch: d_in[0]=edge_feats [N*128] f32, d_in[1]=src [E] i32, d_in[2]=dst [E] i32
// ---------------------------------------------------------------------------
extern "C" void kernel_launch(void* const* d_in, const int* in_sizes, int n_in,
                              void* d_out, int out_size) {
    const float* feats = (const float*)d_in[0];
    const int* src = (const int*)d_in[1];
    const int* dst = (const int*)d_in[2];
    float* out = (float*)d_out;

    const int D = 128;
    const int n_nodes = in_sizes[0] / D;
    const int n_edges = in_sizes[1];
    const long nf4 = (long)n_nodes * (D / 4);
    const int ne4 = n_edges / 4;

    int *cur, *srcs;
    __half* halfp;
    cudaGetSymbolAddress((void**)&cur, g_cur);
    cudaGetSymbolAddress((void**)&srcs, g_srcs);
    cudaGetSymbolAddress((void**)&halfp, g_half);

    // 1. convert + zero cursors
    prep_kernel<<<2048, 256>>>((const float4*)feats, (uint2*)halfp, cur,
                               nf4, n_nodes);
    // 2. bucket fill (4 edges/thread)
    fill_kernel<<<(ne4 + 255) / 256, 256>>>((const int4*)src, (const int4*)dst,
                                            cur, srcs, ne4, n_edges);
    // 3. fp16 pull-gather + fp32 finalize
    {
        long total = (long)n_nodes * 32;
        gather_kernel<<<(int)((total + 255) / 256), 256>>>(
            (const float4*)feats, (const uint2*)halfp, cur, srcs,
            (float4*)out, n_nodes);
    }
}